// round 12
// baseline (speedup 1.0000x reference)
#include <cuda_runtime.h>
#include <cstdint>

#define HPAD   66
#define CIN    128
#define OC     128
#define HW     4096
#define NB     4
#define NS     9
#define NCHUNK 36
#define STAGES 6

// ---- device scratch ----
__device__ float  g_xpad[NB * HPAD * HPAD * CIN + 64];  // NHWC padded x
__device__ float  g_wk2[NS * OC * CIN];                 // [n][oc][c], tf32-rounded
__device__ float4 g_gw[NB * NS * HW];                   // bilinear weights
__device__ int4   g_gi[NB * NS * HW];                   // gather indices (66x66 plane)

// ---- dynamic smem layout (bytes) ----
#define SM_TPTR   0
#define SM_EMPTY(s) (16 + 8 * (s))
#define SM_A(s)   (1024 + (s) * 32768)
#define SM_B(s)   (SM_A(s) + 16384)
#define SM_TS     1024               /* aliases ring stage 0: free when epilogue runs */
#define SM_TOTAL  (1024 + STAGES * 32768)

#define STG_BYTES 32768
#define RING_BYTES (STAGES * STG_BYTES)

#define TMEM_COLS 128
// idesc kind::tf32: dtype=F32(1)<<4, atype=TF32(2)<<7, btype=TF32(2)<<10,
// N>>3 (16)<<17, M>>4 (8)<<24
#define IDESC 0x8200910u

#define SW128(o) ((o) ^ (((o) >> 3) & 0x70))

// Feature gate: tcgen05 only exists in the compute_103a device pass.
#if !defined(__CUDA_ARCH__) || defined(__CUDA_ARCH_FEAT_SM103_ALL)
#define HAS_TCGEN05 1
#else
#define HAS_TCGEN05 0
#endif

// ---------------- PTX helpers ----------------
__device__ __forceinline__ uint32_t smem_u32(const void* p) {
    uint32_t a;
    asm("{ .reg .u64 t; cvta.to.shared.u64 t, %1; cvt.u32.u64 %0, t; }" : "=r"(a) : "l"(p));
    return a;
}
__device__ __forceinline__ float ftf32(float x) {
    uint32_t r; asm("cvt.rna.tf32.f32 %0, %1;" : "=r"(r) : "f"(x));
    return __uint_as_float(r);
}
__device__ __forceinline__ uint64_t mkdesc(uint32_t addr) {
    const uint64_t base = (2ull << 61) | (1ull << 46) | (64ull << 32) | (1ull << 16);
    return base | ((uint64_t)(addr >> 4) & 0x3FFF);
}
__device__ __forceinline__ void mbar_init(uint32_t a, uint32_t cnt) {
    asm volatile("mbarrier.init.shared.b64 [%0], %1;" :: "r"(a), "r"(cnt) : "memory");
}
__device__ __forceinline__ void mbar_wait(uint32_t a, uint32_t par) {
    uint32_t done;
    asm volatile(
        "{\n\t.reg .pred p;\n\t"
        "mbarrier.try_wait.parity.acquire.cta.shared::cta.b64 p, [%1], %2;\n\t"
        "selp.b32 %0, 1, 0, p;\n\t}"
        : "=r"(done) : "r"(a), "r"(par) : "memory");
    if (!done) {
        asm volatile(
            "{\n\t.reg .pred P1;\n\t"
            "W%=:\n\t"
            "mbarrier.try_wait.parity.acquire.cta.shared::cta.b64 P1, [%0], %1, 0x989680;\n\t"
            "@P1 bra.uni D%=;\n\t"
            "bra.uni W%=;\n\t"
            "D%=:\n\t}"
            :: "r"(a), "r"(par) : "memory");
    }
}
__device__ __forceinline__ void nbar_arrive(int id, int cnt) {
    asm volatile("bar.arrive %0, %1;" :: "r"(id), "r"(cnt) : "memory");
}
__device__ __forceinline__ void nbar_sync(int id, int cnt) {
    asm volatile("bar.sync %0, %1;" :: "r"(id), "r"(cnt) : "memory");
}
__device__ __forceinline__ void sts128(uint32_t a, float4 v) {
    asm volatile("st.shared.v4.b32 [%0], {%1,%2,%3,%4};"
                 :: "r"(a), "f"(v.x), "f"(v.y), "f"(v.z), "f"(v.w) : "memory");
}

#if HAS_TCGEN05
__device__ __forceinline__ void mma_tf32(uint32_t d, uint64_t ad, uint64_t bd, bool acc) {
    uint32_t e = acc ? 1u : 0u, z = 0u;
    asm volatile(
        "{\n\t.reg .pred p;\n\tsetp.ne.u32 p, %5, 0;\n\t"
        "tcgen05.mma.cta_group::1.kind::tf32 [%0], %1, %2, %3, {%4,%4,%4,%4}, p;\n\t}"
        :: "r"(d), "l"(ad), "l"(bd), "r"(IDESC), "r"(z), "r"(e) : "memory");
}
__device__ __forceinline__ void mma_commit(uint32_t mbar) {
    asm volatile(
        "tcgen05.commit.cta_group::1.mbarrier::arrive::one.shared::cluster.b64 [%0];"
        :: "r"(mbar) : "memory");
}
__device__ __forceinline__ void ldtm32(uint32_t* r, uint32_t ta) {
    asm volatile(
        "tcgen05.ld.sync.aligned.32x32b.x32.b32 "
        "{%0,%1,%2,%3,%4,%5,%6,%7,%8,%9,%10,%11,%12,%13,%14,%15,"
        "%16,%17,%18,%19,%20,%21,%22,%23,%24,%25,%26,%27,%28,%29,%30,%31}, [%32];"
        : "=r"(r[0]),"=r"(r[1]),"=r"(r[2]),"=r"(r[3]),"=r"(r[4]),"=r"(r[5]),"=r"(r[6]),"=r"(r[7]),
          "=r"(r[8]),"=r"(r[9]),"=r"(r[10]),"=r"(r[11]),"=r"(r[12]),"=r"(r[13]),"=r"(r[14]),"=r"(r[15]),
          "=r"(r[16]),"=r"(r[17]),"=r"(r[18]),"=r"(r[19]),"=r"(r[20]),"=r"(r[21]),"=r"(r[22]),"=r"(r[23]),
          "=r"(r[24]),"=r"(r[25]),"=r"(r[26]),"=r"(r[27]),"=r"(r[28]),"=r"(r[29]),"=r"(r[30]),"=r"(r[31])
        : "r"(ta));
}
#endif

// ---------------- fused prep: pad/transpose (blocks 0..527) + wk/coef (blocks 528..1103) ---
__global__ __launch_bounds__(256) void prep_kernel(const float* __restrict__ x,
                                                   const float* __restrict__ w,
                                                   const float* __restrict__ off) {
    __shared__ float ts[64 * 65];
    int bk  = blockIdx.x;
    int tid = threadIdx.x;
    if (bk < 528) {
        int half = bk & 1, ri = bk >> 1;
        int hp = ri % HPAD, b = ri / HPAD;
        bool irow = (hp >= 1 && hp <= 64);
        if (irow) {
            const float* xr = x + ((size_t)(b * CIN + half * 64)) * 4096 + (size_t)(hp - 1) * 64;
            #pragma unroll
            for (int i = 0; i < 16; i++) {
                int idx = tid + i * 256;
                int c = idx >> 6, wp = idx & 63;
                ts[c * 65 + wp] = xr[(size_t)c * 4096 + wp];
            }
        }
        __syncthreads();
        float* orow = g_xpad + ((size_t)(b * HPAD + hp)) * HPAD * CIN + half * 64;
        #pragma unroll
        for (int i = 0; i < 5; i++) {
            int idx = tid + i * 256;            // over 66*16 = 1056 float4
            if (idx >= 1056) break;
            int wp = idx >> 4, c4i = idx & 15;
            float4 v = make_float4(0.f, 0.f, 0.f, 0.f);
            if (irow && wp >= 1 && wp <= 64) {
                int c = c4i * 4, wq = wp - 1;
                v = make_float4(ts[c * 65 + wq], ts[(c + 1) * 65 + wq],
                                ts[(c + 2) * 65 + wq], ts[(c + 3) * 65 + wq]);
            }
            *(float4*)(orow + (size_t)wp * CIN + c4i * 4) = v;
        }
    } else {
        int t = (bk - 528) * 256 + tid;
        {   // weight: [n][oc][c] <- w[oc][c][n]
            int c  = t & 127;
            int oc = (t >> 7) & 127;
            int n  = t >> 14;
            g_wk2[(n * OC + oc) * CIN + c] = ftf32(w[(oc * CIN + c) * 9 + n]);
        }
        {   // coefs
            int pix = t & 4095;
            int n   = (t >> 12) % 9;
            int b   = t / (9 * 4096);
            int i   = pix >> 6, j = pix & 63;
            float ox = off[(b * 18 + 2 * n)     * HW + pix];
            float oy = off[(b * 18 + 2 * n + 1) * HW + pix];
            float px = (float)(i + n / 3) + ox;
            float py = (float)(j + n % 3) + oy;
            float fx = floorf(px), fy = floorf(py);
            int qltx = min(max((int)fx, 0), 65);
            int qlty = min(max((int)fy, 0), 65);
            int qrbx = min(max((int)fx + 1, 0), 65);
            int qrby = min(max((int)fy + 1, 0), 65);
            if (px < 1.f || px > 64.f) px = fx;
            if (py < 1.f || py > 64.f) py = fy;
            px = fminf(fmaxf(px, 0.f), 65.f);
            py = fminf(fmaxf(py, 0.f), 65.f);
            float dltx = 1.f + (float)qltx - px;
            float dlty = 1.f + (float)qlty - py;
            float drbx = 1.f - ((float)qrbx - px);
            float drby = 1.f - ((float)qrby - py);
            g_gw[t] = make_float4(dltx * dlty, drbx * drby, dltx * drby, drbx * dlty);
            g_gi[t] = make_int4(qltx * HPAD + qlty, qrbx * HPAD + qrby,
                                qltx * HPAD + qrby, qrbx * HPAD + qlty);
        }
    }
}

// ------- main: 31 builder warps (chunk pairs) + MMA warp (builds px 124-127) -------
__global__ __launch_bounds__(1024, 1) void main_kernel(float* __restrict__ out) {
#if HAS_TCGEN05
    extern __shared__ char sm[];
    uint32_t smb = smem_u32(sm);
    int tid  = threadIdx.x;
    int wid  = tid >> 5;
    int lane = tid & 31;
    int b       = blockIdx.x >> 5;
    int pixbase = (blockIdx.x & 31) << 7;

    if (wid == 0)
        asm volatile("tcgen05.alloc.cta_group::1.sync.aligned.shared::cta.b32 [%0], %1;"
                     :: "r"(smb + SM_TPTR), "r"((uint32_t)TMEM_COLS) : "memory");
    if (tid == 0) {
        #pragma unroll
        for (int s = 0; s < STAGES; s++) mbar_init(smb + SM_EMPTY(s), 1);
    }
    __syncthreads();

    uint32_t tmem_base;
    asm volatile("ld.shared.b32 %0, [%1];" : "=r"(tmem_base) : "r"(smb + SM_TPTR));

    const char* xb = (const char*)(g_xpad + (size_t)b * HPAD * HPAD * CIN);

    if (wid == 31) {
        // ------- MMA warp: builds pixels 124..127 slice, then syncs + issues MMA -------
        int c4 = lane & 7;
        int p0 = 124 + (lane >> 3);
        const char* xrow = xb + c4 * 16;
        const float4* gwp = g_gw + ((size_t)b * NS) * HW + pixbase + p0;
        const int4*   gip = g_gi + ((size_t)b * NS) * HW + pixbase + p0;
        const char*   wkp = (const char*)g_wk2 + ((size_t)p0 * CIN + c4 * 4) * 4;
        uint32_t offAB = SW128((uint32_t)(p0 * 128 + c4 * 16));
        uint32_t Ast = smb + 1024 + offAB;
        uint32_t Bst = smb + 1024 + 16384 + offAB;
        uint32_t Aba = smb + 1024;
        uint32_t emb = smb + 16;
        int bid = 1, scnt = 0, grp = 0, par = 0;

        float4 cw = make_float4(0.f, 0.f, 0.f, 0.f);
        const char *r0a = xrow, *r1a = xrow, *r2a = xrow, *r3a = xrow;
        const char* wkn = wkp;
        #pragma unroll 1
        for (int j = 0; j < NCHUNK; j++) {
            int cc = j & 3;
            if (j >= 6) mbar_wait(emb, par);
            if (cc == 0) {
                cw = *gwp; int4 gi = *gip;
                gwp += HW; gip += HW;
                r0a = xrow + gi.x * 512; r1a = xrow + gi.y * 512;
                r2a = xrow + gi.z * 512; r3a = xrow + gi.w * 512;
                wkn = wkp + (size_t)(j >> 2) * 65536;
            }
            asm volatile("cp.async.cg.shared.global [%0], [%1], 16;"
                         :: "r"(Ast), "l"(wkn + cc * 128) : "memory");
            asm volatile("cp.async.commit_group;" ::: "memory");
            {
                int o = cc * 128;
                float4 v0 = *(const float4*)(r0a + o);
                float4 v1 = *(const float4*)(r1a + o);
                float4 v2 = *(const float4*)(r2a + o);
                float4 v3 = *(const float4*)(r3a + o);
                float4 r_;
                r_.x = ftf32(cw.x*v0.x + cw.y*v1.x + cw.z*v2.x + cw.w*v3.x);
                r_.y = ftf32(cw.x*v0.y + cw.y*v1.y + cw.z*v2.y + cw.w*v3.y);
                r_.z = ftf32(cw.x*v0.z + cw.y*v1.z + cw.z*v2.z + cw.w*v3.z);
                r_.w = ftf32(cw.x*v0.w + cw.y*v1.w + cw.z*v2.w + cw.w*v3.w);
                sts128(Bst, r_);
            }
            asm volatile("cp.async.wait_group 0;" ::: "memory");
            asm volatile("fence.proxy.async.shared::cta;" ::: "memory");
            nbar_sync(bid, 1024);
            if (lane == 0) {
                uint64_t ad = mkdesc(Aba);
                uint64_t bd = mkdesc(Aba + 16384);
                #pragma unroll
                for (int k = 0; k < 4; k++)
                    mma_tf32(tmem_base, ad + 2 * k, bd + 2 * k, (j > 0) || (k > 0));
                mma_commit(emb);
            }
            Ast += STG_BYTES; Bst += STG_BYTES; Aba += STG_BYTES; emb += 8; bid++;
            if (++scnt == STAGES) {
                scnt = 0; Ast -= RING_BYTES; Bst -= RING_BYTES; Aba -= RING_BYTES;
                emb -= STAGES * 8; bid -= STAGES; grp++; par = (grp - 1) & 1;
            }
        }
    } else {
        // ------- 31 builder warps: pixels 0..123, chunk pairs -------
        int c4 = tid & 7;
        int p0 = tid >> 3;
        const char* xrow = xb + c4 * 16;
        const float4* gwp = g_gw + ((size_t)b * NS) * HW + pixbase + p0;
        const int4*   gip = g_gi + ((size_t)b * NS) * HW + pixbase + p0;
        const char*   wkp = (const char*)g_wk2 + ((size_t)p0 * CIN + c4 * 4) * 4;
        uint32_t offAB = SW128((uint32_t)(p0 * 128 + c4 * 16));
        uint32_t Ast = smb + 1024 + offAB;
        uint32_t Bst = smb + 1024 + 16384 + offAB;
        uint32_t emb = smb + 16;
        int bid = 1, spair = 0, grp = 0, par = 0, jj = 0;

#define BPAIR(CC0) do {                                                          \
        if (jj >= 6) { mbar_wait(emb, par); mbar_wait(emb + 8, par); }           \
        asm volatile("cp.async.cg.shared.global [%0], [%1], 16;"                 \
                     :: "r"(Ast), "l"(wkn + (CC0) * 128) : "memory");            \
        asm volatile("cp.async.commit_group;" ::: "memory");                     \
        asm volatile("cp.async.cg.shared.global [%0], [%1], 16;"                 \
                     :: "r"(Ast + (uint32_t)STG_BYTES), "l"(wkn + (CC0) * 128 + 128) : "memory"); \
        asm volatile("cp.async.commit_group;" ::: "memory");                     \
        float4 v0 = *(const float4*)(r0a + (CC0) * 128);                         \
        float4 v1 = *(const float4*)(r1a + (CC0) * 128);                         \
        float4 v2 = *(const float4*)(r2a + (CC0) * 128);                         \
        float4 v3 = *(const float4*)(r3a + (CC0) * 128);                         \
        float4 u0 = *(const float4*)(r0a + (CC0) * 128 + 128);                   \
        float4 u1 = *(const float4*)(r1a + (CC0) * 128 + 128);                   \
        float4 u2 = *(const float4*)(r2a + (CC0) * 128 + 128);                   \
        float4 u3 = *(const float4*)(r3a + (CC0) * 128 + 128);                   \
        float4 r_;                                                               \
        r_.x = ftf32(cw.x*v0.x + cw.y*v1.x + cw.z*v2.x + cw.w*v3.x);             \
        r_.y = ftf32(cw.x*v0.y + cw.y*v1.y + cw.z*v2.y + cw.w*v3.y);             \
        r_.z = ftf32(cw.x*v0.z + cw.y*v1.z + cw.z*v2.z + cw.w*v3.z);             \
        r_.w = ftf32(cw.x*v0.w + cw.y*v1.w + cw.z*v2.w + cw.w*v3.w);             \
        sts128(Bst, r_);                                                         \
        asm volatile("cp.async.wait_group 1;" ::: "memory");                     \
        asm volatile("fence.proxy.async.shared::cta;" ::: "memory");             \
        nbar_arrive(bid, 1024);                                                  \
        float4 q_;                                                               \
        q_.x = ftf32(cw.x*u0.x + cw.y*u1.x + cw.z*u2.x + cw.w*u3.x);             \
        q_.y = ftf32(cw.x*u0.y + cw.y*u1.y + cw.z*u2.y + cw.w*u3.y);             \
        q_.z = ftf32(cw.x*u0.z + cw.y*u1.z + cw.z*u2.z + cw.w*u3.z);             \
        q_.w = ftf32(cw.x*u0.w + cw.y*u1.w + cw.z*u2.w + cw.w*u3.w);             \
        sts128(Bst + (uint32_t)STG_BYTES, q_);                                   \
        asm volatile("cp.async.wait_group 0;" ::: "memory");                     \
        asm volatile("fence.proxy.async.shared::cta;" ::: "memory");             \
        nbar_arrive(bid + 1, 1024);                                              \
        jj += 2; Ast += 2 * STG_BYTES; Bst += 2 * STG_BYTES; emb += 16; bid += 2;\
        if (++spair == 3) {                                                      \
            spair = 0; Ast -= RING_BYTES; Bst -= RING_BYTES;                     \
            emb -= STAGES * 8; bid -= STAGES; grp++; par = (grp - 1) & 1;        \
        }                                                                        \
    } while (0)

        #pragma unroll 1
        for (int n = 0; n < NS; n++) {
            float4 cw = *gwp; int4 gi = *gip;
            gwp += HW; gip += HW;
            const char* r0a = xrow + gi.x * 512;
            const char* r1a = xrow + gi.y * 512;
            const char* r2a = xrow + gi.z * 512;
            const char* r3a = xrow + gi.w * 512;
            const char* wkn = wkp + (size_t)n * 65536;
            BPAIR(0);
            BPAIR(2);
        }
#undef BPAIR
    }

    // last chunk j=35 -> stage 5; 6th completion -> parity 1
    mbar_wait(smb + SM_EMPTY(STAGES - 1), (NCHUNK / STAGES - 1) & 1);
    asm volatile("tcgen05.fence::after_thread_sync;" ::: "memory");

    // ---- epilogue: TMEM -> smem transpose -> coalesced STG (Ts aliases ring stage 0) ----
    float* Ts = (float*)(sm + SM_TS);
    for (int cg = 0; cg < 4; cg++) {
        if (wid < 4) {
            uint32_t r[32];
            ldtm32(r, tmem_base + cg * 32);
            asm volatile("tcgen05.wait::ld.sync.aligned;" ::: "memory");
            int oc = wid * 32 + lane;
            #pragma unroll
            for (int c = 0; c < 32; c++) Ts[oc * 33 + c] = __uint_as_float(r[c]);
        }
        __syncthreads();
        {
            int ocr = tid >> 3, q4 = (tid & 7) * 4;
            const float* row = Ts + ocr * 33 + q4;
            float* op = out + ((size_t)(b * OC + ocr)) * HW + pixbase + cg * 32 + q4;
            *(float4*)op = make_float4(row[0], row[1], row[2], row[3]);
        }
        __syncthreads();
    }

    if (wid == 0) {
        asm volatile("tcgen05.relinquish_alloc_permit.cta_group::1.sync.aligned;");
        asm volatile("tcgen05.dealloc.cta_group::1.sync.aligned.b32 %0, %1;"
                     :: "r"(tmem_base), "r"((uint32_t)TMEM_COLS));
    }
#else
    (void)out;   // non-103a PTX pass: dead body; sm_103a cubin selected at runtime
#endif
}

// ---------------- launch ----------------
extern "C" void kernel_launch(void* const* d_in, const int* in_sizes, int n_in,
                              void* d_out, int out_size) {
    const float* x   = (const float*)d_in[0];
    const float* off = (const float*)d_in[1];
    const float* w   = (const float*)d_in[2];
    float* out = (float*)d_out;
    (void)in_sizes; (void)n_in; (void)out_size;

    cudaFuncSetAttribute(main_kernel, cudaFuncAttributeMaxDynamicSharedMemorySize, SM_TOTAL);

    prep_kernel<<<528 + 576, 256>>>(x, w, off);
    main_kernel<<<128, 1024, SM_TOTAL>>>(out);
}

// round 13
// speedup vs baseline: 1.8076x; 1.8076x over previous
#include <cuda_runtime.h>
#include <cuda_fp16.h>
#include <cstdint>

#define HPAD   66
#define CIN    128
#define OC     128
#define HW     4096
#define NB     4
#define NS     9
#define NCHUNK 18            /* 9 n x 2 channel-halves, K=64 fp16 per chunk */
#define STAGES 6

// ---- device scratch (16B-aligned via uint4) ----
__device__ uint4 g_xpad4[NB * HPAD * HPAD * CIN * 2 / 16 + 16]; // NHWC fp16 padded x
__device__ uint4 g_wk4[NS * 2 * OC * 64 * 2 / 16];              // [n][half][oc][64ch] fp16
__device__ float4 g_gw[NB * NS * HW];                           // bilinear weights
__device__ int4   g_gi[NB * NS * HW];                           // gather indices

// ---- dynamic smem layout (bytes) ----
#define SM_TPTR   0
#define SM_EMPTY(s) (16 + 8 * (s))
#define SM_FULL(s)  (64 + 8 * (s))
#define SM_A(s)   (1024 + (s) * 32768)          /* 128oc x 64ch fp16 = 16KB */
#define SM_B(s)   (SM_A(s) + 16384)             /* 128px x 64ch fp16 = 16KB */
#define SM_TS     1024
#define SM_TOTAL  (1024 + STAGES * 32768)

#define TMEM_COLS 128
// idesc kind::f16 (fp16 in, fp32 acc): dtype=F32(1)<<4, atype=FP16(0), btype=FP16(0),
// (N/8)<<17, (M/16)<<24
#define IDESC 0x8200010u

#define SW128(o) ((o) ^ (((o) >> 3) & 0x70))

#if !defined(__CUDA_ARCH__) || defined(__CUDA_ARCH_FEAT_SM103_ALL)
#define HAS_TCGEN05 1
#else
#define HAS_TCGEN05 0
#endif

// ---------------- PTX helpers ----------------
__device__ __forceinline__ uint32_t smem_u32(const void* p) {
    uint32_t a;
    asm("{ .reg .u64 t; cvta.to.shared.u64 t, %1; cvt.u32.u64 %0, t; }" : "=r"(a) : "l"(p));
    return a;
}
__device__ __forceinline__ uint64_t mkdesc(uint32_t addr) {
    const uint64_t base = (2ull << 61) | (1ull << 46) | (64ull << 32) | (1ull << 16);
    return base | ((uint64_t)(addr >> 4) & 0x3FFF);
}
__device__ __forceinline__ void mbar_init(uint32_t a, uint32_t cnt) {
    asm volatile("mbarrier.init.shared.b64 [%0], %1;" :: "r"(a), "r"(cnt) : "memory");
}
__device__ __forceinline__ void mbar_arrive(uint32_t a) {
    asm volatile("mbarrier.arrive.shared.b64 _, [%0];" :: "r"(a) : "memory");
}
__device__ __forceinline__ void mbar_wait(uint32_t a, uint32_t par) {
    uint32_t done;
    asm volatile(
        "{\n\t.reg .pred p;\n\t"
        "mbarrier.try_wait.parity.acquire.cta.shared::cta.b64 p, [%1], %2;\n\t"
        "selp.b32 %0, 1, 0, p;\n\t}"
        : "=r"(done) : "r"(a), "r"(par) : "memory");
    if (!done) {
        asm volatile(
            "{\n\t.reg .pred P1;\n\t"
            "W%=:\n\t"
            "mbarrier.try_wait.parity.acquire.cta.shared::cta.b64 P1, [%0], %1, 0x989680;\n\t"
            "@P1 bra.uni D%=;\n\t"
            "bra.uni W%=;\n\t"
            "D%=:\n\t}"
            :: "r"(a), "r"(par) : "memory");
    }
}
__device__ __forceinline__ void sts128u(uint32_t a, uint4 v) {
    asm volatile("st.shared.v4.b32 [%0], {%1,%2,%3,%4};"
                 :: "r"(a), "r"(v.x), "r"(v.y), "r"(v.z), "r"(v.w) : "memory");
}
__device__ __forceinline__ float2 h2f(uint32_t h) {
    __half2 v = *(__half2*)&h;
    return __half22float2(v);
}
__device__ __forceinline__ uint32_t bil2(float4 cw, uint32_t w0, uint32_t w1,
                                         uint32_t w2, uint32_t w3) {
    float2 f0 = h2f(w0), f1 = h2f(w1), f2 = h2f(w2), f3 = h2f(w3);
    float rx = cw.x * f0.x + cw.y * f1.x + cw.z * f2.x + cw.w * f3.x;
    float ry = cw.x * f0.y + cw.y * f1.y + cw.z * f2.y + cw.w * f3.y;
    __half2 h = __floats2half2_rn(rx, ry);
    return *(uint32_t*)&h;
}

#if HAS_TCGEN05
__device__ __forceinline__ void mma_f16(uint32_t d, uint64_t ad, uint64_t bd, bool acc) {
    uint32_t e = acc ? 1u : 0u, z = 0u;
    asm volatile(
        "{\n\t.reg .pred p;\n\tsetp.ne.u32 p, %5, 0;\n\t"
        "tcgen05.mma.cta_group::1.kind::f16 [%0], %1, %2, %3, {%4,%4,%4,%4}, p;\n\t}"
        :: "r"(d), "l"(ad), "l"(bd), "r"(IDESC), "r"(z), "r"(e) : "memory");
}
__device__ __forceinline__ void mma_commit(uint32_t mbar) {
    asm volatile(
        "tcgen05.commit.cta_group::1.mbarrier::arrive::one.shared::cluster.b64 [%0];"
        :: "r"(mbar) : "memory");
}
__device__ __forceinline__ void ldtm32(uint32_t* r, uint32_t ta) {
    asm volatile(
        "tcgen05.ld.sync.aligned.32x32b.x32.b32 "
        "{%0,%1,%2,%3,%4,%5,%6,%7,%8,%9,%10,%11,%12,%13,%14,%15,"
        "%16,%17,%18,%19,%20,%21,%22,%23,%24,%25,%26,%27,%28,%29,%30,%31}, [%32];"
        : "=r"(r[0]),"=r"(r[1]),"=r"(r[2]),"=r"(r[3]),"=r"(r[4]),"=r"(r[5]),"=r"(r[6]),"=r"(r[7]),
          "=r"(r[8]),"=r"(r[9]),"=r"(r[10]),"=r"(r[11]),"=r"(r[12]),"=r"(r[13]),"=r"(r[14]),"=r"(r[15]),
          "=r"(r[16]),"=r"(r[17]),"=r"(r[18]),"=r"(r[19]),"=r"(r[20]),"=r"(r[21]),"=r"(r[22]),"=r"(r[23]),
          "=r"(r[24]),"=r"(r[25]),"=r"(r[26]),"=r"(r[27]),"=r"(r[28]),"=r"(r[29]),"=r"(r[30]),"=r"(r[31])
        : "r"(ta));
}
#endif

// ---------------- fused prep: pad/transpose->fp16 (0..527) + wk/coef (528..1103) ----------
__global__ __launch_bounds__(256) void prep_kernel(const float* __restrict__ x,
                                                   const float* __restrict__ w,
                                                   const float* __restrict__ off) {
    __shared__ float ts[64 * 65];
    int bk  = blockIdx.x;
    int tid = threadIdx.x;
    if (bk < 528) {
        int half = bk & 1, ri = bk >> 1;
        int hp = ri % HPAD, b = ri / HPAD;
        bool irow = (hp >= 1 && hp <= 64);
        if (irow) {
            const float* xr = x + ((size_t)(b * CIN + half * 64)) * 4096 + (size_t)(hp - 1) * 64;
            #pragma unroll
            for (int i = 0; i < 16; i++) {
                int idx = tid + i * 256;
                int c = idx >> 6, wp = idx & 63;
                ts[c * 65 + wp] = xr[(size_t)c * 4096 + wp];
            }
        }
        __syncthreads();
        __half* orow = (__half*)g_xpad4 + ((size_t)(b * HPAD + hp)) * HPAD * CIN + half * 64;
        #pragma unroll
        for (int i = 0; i < 3; i++) {
            int idx = tid + i * 256;            // over 66*8 = 528 uint4 (8 halves each)
            if (idx >= 528) break;
            int wp = idx >> 3, g = idx & 7;
            uint4 v = make_uint4(0, 0, 0, 0);
            if (irow && wp >= 1 && wp <= 64) {
                int c = g * 8, wq = wp - 1;
                __half2 h0 = __floats2half2_rn(ts[(c+0)*65+wq], ts[(c+1)*65+wq]);
                __half2 h1 = __floats2half2_rn(ts[(c+2)*65+wq], ts[(c+3)*65+wq]);
                __half2 h2 = __floats2half2_rn(ts[(c+4)*65+wq], ts[(c+5)*65+wq]);
                __half2 h3 = __floats2half2_rn(ts[(c+6)*65+wq], ts[(c+7)*65+wq]);
                v.x = *(uint32_t*)&h0; v.y = *(uint32_t*)&h1;
                v.z = *(uint32_t*)&h2; v.w = *(uint32_t*)&h3;
            }
            *(uint4*)(orow + (size_t)wp * CIN + g * 8) = v;
        }
    } else {
        int t = (bk - 528) * 256 + tid;
        {   // weight: [n][half][oc][64] fp16 <- w[oc][c][n]
            int c  = t & 127;
            int oc = (t >> 7) & 127;
            int n  = t >> 14;
            __half* wk = (__half*)g_wk4;
            wk[(((size_t)n * 2 + (c >> 6)) * OC + oc) * 64 + (c & 63)] =
                __float2half_rn(w[(oc * CIN + c) * 9 + n]);
        }
        {   // coefs
            int pix = t & 4095;
            int n   = (t >> 12) % 9;
            int b   = t / (9 * 4096);
            int i   = pix >> 6, j = pix & 63;
            float ox = off[(b * 18 + 2 * n)     * HW + pix];
            float oy = off[(b * 18 + 2 * n + 1) * HW + pix];
            float px = (float)(i + n / 3) + ox;
            float py = (float)(j + n % 3) + oy;
            float fx = floorf(px), fy = floorf(py);
            int qltx = min(max((int)fx, 0), 65);
            int qlty = min(max((int)fy, 0), 65);
            int qrbx = min(max((int)fx + 1, 0), 65);
            int qrby = min(max((int)fy + 1, 0), 65);
            if (px < 1.f || px > 64.f) px = fx;
            if (py < 1.f || py > 64.f) py = fy;
            px = fminf(fmaxf(px, 0.f), 65.f);
            py = fminf(fmaxf(py, 0.f), 65.f);
            float dltx = 1.f + (float)qltx - px;
            float dlty = 1.f + (float)qlty - py;
            float drbx = 1.f - ((float)qrbx - px);
            float drby = 1.f - ((float)qrby - py);
            g_gw[t] = make_float4(dltx * dlty, drbx * drby, dltx * drby, drbx * dlty);
            g_gi[t] = make_int4(qltx * HPAD + qlty, qrbx * HPAD + qrby,
                                qltx * HPAD + qrby, qrbx * HPAD + qlty);
        }
    }
}

// ------- main: two 8-warp builder sets on alternating K=64 fp16 chunks + MMA warp -------
__global__ __launch_bounds__(544, 1) void main_kernel(float* __restrict__ out) {
#if HAS_TCGEN05
    extern __shared__ char sm[];
    uint32_t smb = smem_u32(sm);
    int tid  = threadIdx.x;
    int wid  = tid >> 5;
    int lane = tid & 31;
    int b       = blockIdx.x >> 5;
    int pixbase = (blockIdx.x & 31) << 7;

    if (wid == 0)
        asm volatile("tcgen05.alloc.cta_group::1.sync.aligned.shared::cta.b32 [%0], %1;"
                     :: "r"(smb + SM_TPTR), "r"((uint32_t)TMEM_COLS) : "memory");
    if (tid == 0) {
        #pragma unroll
        for (int s = 0; s < STAGES; s++) {
            mbar_init(smb + SM_EMPTY(s), 1);    // armed by tcgen05.commit
            mbar_init(smb + SM_FULL(s), 8);     // one elected arrival per owning-set warp
        }
    }
    __syncthreads();

    uint32_t tmem_base;
    asm volatile("ld.shared.b32 %0, [%1];" : "=r"(tmem_base) : "r"(smb + SM_TPTR));

    if (wid == 16) {
        // ---------------- dedicated MMA issuer warp ----------------
        if (lane == 0) {
            for (int j = 0; j < NCHUNK; j++) {
                int s = j % STAGES;
                mbar_wait(smb + SM_FULL(s), (j / STAGES) & 1);
                uint64_t ad = mkdesc(smb + SM_A(s));
                uint64_t bd = mkdesc(smb + SM_B(s));
                #pragma unroll
                for (int k = 0; k < 4; k++)      // K=64 = 4 x K16
                    mma_f16(tmem_base, ad + 2 * k, bd + 2 * k, (j > 0) || (k > 0));
                mma_commit(smb + SM_EMPTY(s));
            }
        }
    } else {
        // ---- builder set (8 warps, 256 thr): set 0 -> even chunks (ch half 0),
        //      set 1 -> odd chunks (ch half 1). Chunk j: n = j>>1, stage = j%6. ----
        int setid = wid >> 3;                   // 0 or 1
        int gtid  = (wid & 7) * 32 + lane;      // 0..255
        int c4    = gtid & 7;                   // 16B group (8 fp16 ch of the 64)
        int r0    = gtid >> 3;                  // 0..31 -> pixels r0 + 32k

        const char* xb   = (const char*)g_xpad4 + (size_t)b * HPAD * HPAD * CIN * 2;
        const char* xrow = xb + setid * 128 + c4 * 16;
        const char* wks  = (const char*)g_wk4 + setid * 16384 + c4 * 16;

        float4 cw[4]; int4 ci[4];

        #pragma unroll 1
        for (int m = 0; m < 9; m++) {
            int j = 2 * m + setid;
            int s = j % STAGES;
            if (j >= STAGES) mbar_wait(smb + SM_EMPTY(s), (j / STAGES - 1) & 1);

            // ---- A tile via cp.async: rows r0+32k, 16B column c4 ----
            {
                const char* wkb = wks + (size_t)m * 32768;
                #pragma unroll
                for (int k = 0; k < 4; k++) {
                    int oc = r0 + 32 * k;
                    uint32_t d = smb + SM_A(s) + SW128(oc * 128 + c4 * 16);
                    asm volatile("cp.async.cg.shared.global [%0], [%1], 16;"
                                 :: "r"(d), "l"(wkb + (size_t)oc * 128) : "memory");
                }
                asm volatile("cp.async.commit_group;" ::: "memory");
            }

            // ---- coefs for n = m ----
            {
                const float4* gwp = g_gw + ((size_t)b * NS + m) * HW + pixbase;
                const int4*   gip = g_gi + ((size_t)b * NS + m) * HW + pixbase;
                #pragma unroll
                for (int k = 0; k < 4; k++) {
                    cw[k] = gwp[r0 + 32 * k];
                    ci[k] = gip[r0 + 32 * k];
                }
            }

            // ---- B tile: 4 pixels, 16 gathers of 16B fp16 ----
            char* Bs = sm + SM_B(s);
            #pragma unroll
            for (int k = 0; k < 4; k++) {
                int p = r0 + 32 * k;
                uint4 v0 = *(const uint4*)(xrow + (size_t)ci[k].x * 256);
                uint4 v1 = *(const uint4*)(xrow + (size_t)ci[k].y * 256);
                uint4 v2 = *(const uint4*)(xrow + (size_t)ci[k].z * 256);
                uint4 v3 = *(const uint4*)(xrow + (size_t)ci[k].w * 256);
                uint4 o;
                o.x = bil2(cw[k], v0.x, v1.x, v2.x, v3.x);
                o.y = bil2(cw[k], v0.y, v1.y, v2.y, v3.y);
                o.z = bil2(cw[k], v0.z, v1.z, v2.z, v3.z);
                o.w = bil2(cw[k], v0.w, v1.w, v2.w, v3.w);
                sts128u(smem_u32(Bs) + SW128((uint32_t)(p * 128 + c4 * 16)), o);
            }

            asm volatile("cp.async.wait_group 0;" ::: "memory");
            asm volatile("fence.proxy.async.shared::cta;" ::: "memory");
            __syncwarp();
            if (lane == 0) mbar_arrive(smb + SM_FULL(s));
        }
    }

    // last chunk j=17 -> stage 5; 3rd completion of empty[5] -> wait parity (3-1)&1 = 0
    mbar_wait(smb + SM_EMPTY(STAGES - 1), (NCHUNK / STAGES - 1) & 1);
    asm volatile("tcgen05.fence::after_thread_sync;" ::: "memory");

    // ---- epilogue: TMEM -> smem transpose -> coalesced STG (Ts aliases ring stage 0) ----
    float* Ts = (float*)(sm + SM_TS);
    for (int cg = 0; cg < 4; cg++) {
        if (wid < 4) {
            uint32_t r[32];
            ldtm32(r, tmem_base + cg * 32);
            asm volatile("tcgen05.wait::ld.sync.aligned;" ::: "memory");
            int oc = wid * 32 + lane;
            #pragma unroll
            for (int c = 0; c < 32; c++) Ts[oc * 33 + c] = __uint_as_float(r[c]);
        }
        __syncthreads();
        if (tid < 512) {
            int ocr = tid >> 2, q8 = (tid & 3) * 8;
            const float* row = Ts + ocr * 33 + q8;
            float* op = out + ((size_t)(b * OC + ocr)) * HW + pixbase + cg * 32 + q8;
            *(float4*)(op)     = make_float4(row[0], row[1], row[2], row[3]);
            *(float4*)(op + 4) = make_float4(row[4], row[5], row[6], row[7]);
        }
        __syncthreads();
    }

    if (wid == 0) {
        asm volatile("tcgen05.relinquish_alloc_permit.cta_group::1.sync.aligned;");
        asm volatile("tcgen05.dealloc.cta_group::1.sync.aligned.b32 %0, %1;"
                     :: "r"(tmem_base), "r"((uint32_t)TMEM_COLS));
    }
#else
    (void)out;   // non-103a PTX pass: dead body; sm_103a cubin selected at runtime
#endif
}

// ---------------- launch ----------------
extern "C" void kernel_launch(void* const* d_in, const int* in_sizes, int n_in,
                              void* d_out, int out_size) {
    const float* x   = (const float*)d_in[0];
    const float* off = (const float*)d_in[1];
    const float* w   = (const float*)d_in[2];
    float* out = (float*)d_out;
    (void)in_sizes; (void)n_in; (void)out_size;

    cudaFuncSetAttribute(main_kernel, cudaFuncAttributeMaxDynamicSharedMemorySize, SM_TOTAL);

    prep_kernel<<<528 + 576, 256>>>(x, w, off);
    main_kernel<<<128, 544, SM_TOTAL>>>(out);
}